// round 14
// baseline (speedup 1.0000x reference)
#include <cuda_runtime.h>
#include <cuda_fp16.h>
#include <cstdint>

#define B_DIM 4
#define S_LEN 4096
#define D_DIM 1024
#define N2    4096          // complex FFT size (real FFT of 8192)
#define FNT   256           // threads for FFT kernels (radix-16, 16 pts/thread)
#define KF_PITCH 4104
#define SK(i) ((i) + ((i) >> 3))                 // bank-skewed smem index
#define FFT_SMEM (2 * 4608 * 8)                  // 73728 bytes -> 3 CTAs/SM

// ---------------- scratch (static __device__: allocation-free) ----------------
__device__ float  g_ut[(size_t)B_DIM * D_DIM * S_LEN];   // u transposed (B,D,S)
__device__ float  g_yT[(size_t)B_DIM * D_DIM * S_LEN];   // conv result (B,D,S)
__device__ __half g_uh[(size_t)B_DIM * S_LEN * D_DIM];   // fp16 u (B,S,D)
__device__ __half g_wh[(size_t)D_DIM * D_DIM];           // fp16 W
__device__ float2 g_kf[(size_t)D_DIM * KF_PITCH];        // filter spectra
__device__ float2 g_twh[2048];                            // e^{-2pi i k/4096}
__device__ float2 g_twp[4096];                            // e^{-2pi i k/8192}

// ---------------- utils ----------------
__device__ __forceinline__ uint32_t smem_u32(const void* p) {
    uint32_t a;
    asm("{ .reg .u64 t; cvta.to.shared.u64 t, %1; cvt.u32.u64 %0, t; }"
        : "=r"(a) : "l"(p));
    return a;
}

#define SMEM_SWZ(off) ((off) ^ (((off) >> 3) & 0x70))

__device__ __forceinline__ void cp16(uint32_t saddr, const void* gaddr) {
    asm volatile("cp.async.cg.shared.global [%0], [%1], 16;"
                 :: "r"(saddr), "l"(gaddr) : "memory");
}

__device__ __forceinline__ float2 cmulf(float2 a, float2 w) {
    return make_float2(a.x * w.x - a.y * w.y, a.x * w.y + a.y * w.x);
}

// twiddle tables + fp16 W conversion, one launch
__global__ void prep_kernel(const float* __restrict__ W) {
    int i = blockIdx.x * blockDim.x + threadIdx.x;
    if (i < 2048) {
        float s, c;
        sincospif(-2.0f * (float)i / 4096.0f, &s, &c);
        g_twh[i] = make_float2(c, s);
    }
    if (i < 4096) {
        float s, c;
        sincospif(-2.0f * (float)i / 8192.0f, &s, &c);
        g_twp[i] = make_float2(c, s);
    }
    if (i < D_DIM * D_DIM) g_wh[i] = __float2half_rn(W[i]);
}

// u (B,S,D) -> g_ut (B,D,S); also emit fp16 copy of u (B,S,D)
__global__ void transpose_u(const float* __restrict__ u) {
    __shared__ float t[32][33];
    int b = blockIdx.z;
    int d0 = blockIdx.x * 32, s0 = blockIdx.y * 32;
    int tx = threadIdx.x, ty = threadIdx.y;
#pragma unroll
    for (int j = 0; j < 32; j += 8) {
        size_t idx = ((size_t)(b * S_LEN + s0 + ty + j)) * D_DIM + d0 + tx;
        float v = u[idx];
        t[ty + j][tx] = v;
        g_uh[idx] = __float2half_rn(v);
    }
    __syncthreads();
#pragma unroll
    for (int j = 0; j < 32; j += 8) {
        g_ut[((size_t)(b * D_DIM + d0 + ty + j)) * S_LEN + s0 + tx] = t[tx][ty + j];
    }
}

// ---------------- radix-16 building blocks ------------------------------------
// dft4 in place over (a,b,c,d) = (x[n], x[n+4], x[n+8], x[n+12]); outputs k=0..3
__device__ __forceinline__ void dft4(float2& a, float2& b, float2& c, float2& d,
                                     float dir) {
    float apx = a.x + c.x, apy = a.y + c.y, amx = a.x - c.x, amy = a.y - c.y;
    float bpx = b.x + d.x, bpy = b.y + d.y, bmx = b.x - d.x, bmy = b.y - d.y;
    a = make_float2(apx + bpx, apy + bpy);
    b = make_float2(amx + dir * bmy, amy - dir * bmx);
    c = make_float2(apx - bpx, apy - bpy);
    d = make_float2(amx - dir * bmy, amy + dir * bmx);
}

// internal DFT16 twiddles: v[n0+4k0] *= omega16^{n0*k0}
__device__ __forceinline__ void tw16(float2 v[16], float d) {
    const float c1 = 0.9238795325112867f, s1 = 0.3826834323650898f;
    const float Cc = 0.7071067811865476f;
    v[5]  = cmulf(v[5],  make_float2(c1, -d * s1));
    v[9]  = cmulf(v[9],  make_float2(Cc, -d * Cc));
    v[13] = cmulf(v[13], make_float2(s1, -d * c1));
    v[6]  = cmulf(v[6],  make_float2(Cc, -d * Cc));
    v[10] = make_float2(d * v[10].y, -d * v[10].x);     // * (0, -d)
    v[14] = cmulf(v[14], make_float2(-Cc, -d * Cc));
    v[7]  = cmulf(v[7],  make_float2(s1, -d * c1));
    v[11] = cmulf(v[11], make_float2(-Cc, -d * Cc));
    v[15] = cmulf(v[15], make_float2(-c1, d * s1));
}

// first level: 4 strided dft4s + internal twiddles (in place)
__device__ __forceinline__ void level1(float2 v[16], float dir) {
    dft4(v[0], v[4], v[8],  v[12], dir);
    dft4(v[1], v[5], v[9],  v[13], dir);
    dft4(v[2], v[6], v[10], v[14], dir);
    dft4(v[3], v[7], v[11], v[15], dir);
    tw16(v, dir);
}

__device__ __forceinline__ void load16(float2 v[16], const float2* src, int t) {
#pragma unroll
    for (int m = 0; m < 16; m++) v[m] = src[SK(t + 256 * m)];
}

// second level + outer Stockham twiddle (w^m) + store to smem at o + s*m
__device__ __forceinline__ void stage_store(float2* dst, int o, int s,
                                            float2 v[16], float2 w, float dir) {
    float2 w2 = cmulf(w, w);
    float2 w4 = cmulf(w2, w2);
    float2 wk = make_float2(1.f, 0.f);
#pragma unroll
    for (int k0 = 0; k0 < 4; k0++) {
        float2 p0 = v[4 * k0], p1 = v[4 * k0 + 1];
        float2 p2 = v[4 * k0 + 2], p3 = v[4 * k0 + 3];
        dft4(p0, p1, p2, p3, dir);
        float2 wm = wk;
        dst[SK(o + s * k0)]        = cmulf(p0, wm); wm = cmulf(wm, w4);
        dst[SK(o + s * (k0 + 4))]  = cmulf(p1, wm); wm = cmulf(wm, w4);
        dst[SK(o + s * (k0 + 8))]  = cmulf(p2, wm); wm = cmulf(wm, w4);
        dst[SK(o + s * (k0 + 12))] = cmulf(p3, wm);
        wk = cmulf(wk, w);
    }
}

// forward FFT (3 stages); input from global (top half zero); result -> X regs
__device__ __forceinline__ void fwd_fft(const float2* __restrict__ gin,
                                        float2* A, float2* B, int t, float2 X[16]) {
    float2 v[16];
    // stage 0 (s=1): groups (a, b, 0, 0) -> cheap first level
#pragma unroll
    for (int n0 = 0; n0 < 4; n0++) {
        float2 a = gin[t + 256 * n0];
        float2 b = gin[t + 256 * n0 + 1024];
        v[n0]      = make_float2(a.x + b.x, a.y + b.y);
        v[n0 + 4]  = make_float2(a.x + b.y, a.y - b.x);
        v[n0 + 8]  = make_float2(a.x - b.x, a.y - b.y);
        v[n0 + 12] = make_float2(a.x - b.y, a.y + b.x);
    }
    tw16(v, 1.f);
    stage_store(A, 16 * t, 1, v, __ldg(&g_twh[t]), 1.f);
    __syncthreads();
    // stage 1 (s=16): A -> B
    load16(v, A, t);
    level1(v, 1.f);
    {
        int q = t & 15, ps = t - q;
        stage_store(B, 16 * ps + q, 16, v, __ldg(&g_twh[ps]), 1.f);
    }
    __syncthreads();
    // stage 2 (s=256, ps=0): twiddle-free, in-thread -> X regs
    load16(v, B, t);
    level1(v, 1.f);
#pragma unroll
    for (int k0 = 0; k0 < 4; k0++) {
        float2 p0 = v[4 * k0], p1 = v[4 * k0 + 1];
        float2 p2 = v[4 * k0 + 2], p3 = v[4 * k0 + 3];
        dft4(p0, p1, p2, p3, 1.f);
        X[k0] = p0; X[k0 + 4] = p1; X[k0 + 8] = p2; X[k0 + 12] = p3;
    }
}

// ---------------- filter spectrum: kf[d][k] = F_8192(filt_d zero-padded)[k]/8192
__global__ void __launch_bounds__(FNT, 3)
filt_kernel(const float* __restrict__ filt) {
    extern __shared__ float2 zsm[];
    float2* A = zsm;
    float2* B = zsm + 4608;
    int t = threadIdx.x;
    int d = blockIdx.x;
    const float2* x = (const float2*)(filt + (size_t)d * S_LEN);

    float2 X[16];
    fwd_fft(x, A, B, t, X);      // X[m] = Z[t + 256m]

    // exchange for conjugate mirrors
#pragma unroll
    for (int m = 0; m < 16; m++) A[SK(t + 256 * m)] = X[m];
    __syncthreads();

    const float inv = 1.0f / 8192.0f;
    float2* kf = g_kf + (size_t)d * KF_PITCH;
#pragma unroll
    for (int m = 0; m < 16; m++) {
        int k = t + 256 * m;
        int mi = (t == 0) ? (256 * ((16 - m) & 15)) : ((256 - t) + 256 * (15 - m));
        float2 Zm = A[SK(mi)];
        if (k == 0) {
            kf[0]    = make_float2((X[0].x + X[0].y) * inv, 0.f);
            kf[4096] = make_float2((X[0].x - X[0].y) * inv, 0.f);
        } else {
            float2 Zk = X[m];
            float zmr = Zm.x, zmi = -Zm.y;
            float er = 0.5f * (Zk.x + zmr), ei = 0.5f * (Zk.y + zmi);
            float odr = Zk.x - zmr, odi = Zk.y - zmi;
            float orr = 0.5f * odi, oii = -0.5f * odr;   // O = -i/2*(Zk - conj(Zm))
            float2 w = __ldg(&g_twp[k]);
            float wor = w.x * orr - w.y * oii;
            float woi = w.x * oii + w.y * orr;
            kf[k] = make_float2((er + wor) * inv, (ei + woi) * inv);  // U_k / 8192
        }
    }
}

// ---------------- conv: y[b,d,:] = causal conv(u[b,d,:], filt[d,:]) -----------
__global__ void __launch_bounds__(FNT, 3)
conv_kernel() {
    extern __shared__ float2 zsm[];
    float2* A = zsm;
    float2* B = zsm + 4608;
    int t = threadIdx.x;
    int row = blockIdx.x;                   // b*D + d
    int d = row & (D_DIM - 1);
    const float2* gin = (const float2*)(g_ut + (size_t)row * S_LEN);

    float2 X[16];
    fwd_fft(gin, A, B, t, X);    // X[m] = Z[t + 256m]

    // exchange Z for conjugate mirrors
#pragma unroll
    for (int m = 0; m < 16; m++) A[SK(t + 256 * m)] = X[m];
    __syncthreads();

    // spectral multiply (uniform per-k; only k=0 special), result back into X
    const float2* kf = g_kf + (size_t)d * KF_PITCH;
#pragma unroll
    for (int m = 0; m < 16; m++) {
        int k = t + 256 * m;
        int mi = (t == 0) ? (256 * ((16 - m) & 15)) : ((256 - t) + 256 * (15 - m));
        float2 Zm = A[SK(mi)];
        if (k == 0) {
            float U1 = X[0].x + X[0].y, U2 = X[0].x - X[0].y;
            float2 k0f = __ldg(&kf[0]), kNf = __ldg(&kf[4096]);
            float v1r = U1 * k0f.x, v1i = U1 * k0f.y;
            float v2r = U2 * kNf.x, v2i = U2 * kNf.y;
            float epr = 0.5f * (v1r + v2r), epi = 0.5f * (v1i - v2i);
            float opr = 0.5f * (v1r - v2r), opi = 0.5f * (v1i + v2i);  // W^0 = 1
            X[0] = make_float2(epr - opi, epi + opr);
        } else {
            float2 Zk = X[m];
            float zmr = Zm.x, zmi = -Zm.y;
            float er = 0.5f * (Zk.x + zmr), ei = 0.5f * (Zk.y + zmi);
            float odr = Zk.x - zmr, odi = Zk.y - zmi;
            float orr = 0.5f * odi, oii = -0.5f * odr;
            float2 w = __ldg(&g_twp[k]);
            float wor = w.x * orr - w.y * oii;
            float woi = w.x * oii + w.y * orr;
            float u1r = er + wor, u1i = ei + woi;        // U_k
            float u2r = er - wor, u2i = -(ei - woi);     // U_{4096-k}
            float2 kk  = __ldg(&kf[k]);
            float2 kkm = __ldg(&kf[4096 - k]);
            float v1r = u1r * kk.x  - u1i * kk.y,  v1i = u1r * kk.y  + u1i * kk.x;
            float v2r = u2r * kkm.x - u2i * kkm.y, v2i = u2r * kkm.y + u2i * kkm.x;
            float epr = 0.5f * (v1r + v2r), epi = 0.5f * (v1i - v2i); // E'
            float tr  = 0.5f * (v1r - v2r), ti  = 0.5f * (v1i + v2i);
            float opr = w.x * tr + w.y * ti;                           // conj(W)*T
            float opi = w.x * ti - w.y * tr;
            X[m] = make_float2(epr - opi, epi + opr);    // Z'[k]
        }
    }

    // inverse FFT: st0 from regs -> B, st1 B -> A, st2 A -> global (n<2048, x2)
    level1(X, -1.f);
    {
        float2 w = __ldg(&g_twh[t]);
        stage_store(B, 16 * t, 1, X, make_float2(w.x, -w.y), -1.f);
    }
    __syncthreads();
    float2 v[16];
    load16(v, B, t);
    level1(v, -1.f);
    {
        int q = t & 15, ps = t - q;
        float2 w = __ldg(&g_twh[ps]);
        stage_store(A, 16 * ps + q, 16, v, make_float2(w.x, -w.y), -1.f);
    }
    __syncthreads();
    load16(v, A, t);
    level1(v, -1.f);
    float2* gout = (float2*)(g_yT + (size_t)row * S_LEN);
#pragma unroll
    for (int k0 = 0; k0 < 4; k0++) {         // keep k1=0,1 only (n < 2048)
        float2 p0 = v[4 * k0], p1 = v[4 * k0 + 1];
        float2 p2 = v[4 * k0 + 2], p3 = v[4 * k0 + 3];
        float apx = p0.x + p2.x, apy = p0.y + p2.y;
        float amx = p0.x - p2.x, amy = p0.y - p2.y;
        float bpx = p1.x + p3.x, bpy = p1.y + p3.y;
        float bmx = p1.x - p3.x, bmy = p1.y - p3.y;
        gout[t + 256 * k0]       = make_float2(2.f * (apx + bpx), 2.f * (apy + bpy));
        gout[t + 256 * (k0 + 4)] = make_float2(2.f * (amx - bmy), 2.f * (amy + bmx));
    }
}

// ---------------- GEMM: mma.sync fp16 m16n8k16, 3-stage cp.async, ldmatrix ----
// C[16384,1024] = g_uh @ g_wh^T (fp32 acc); out = yconv * (C + bias) + u
// yconv tile staged from g_yT (B,D,S) into smem (no transpose_y kernel).
#define GS_STAGE 32768                    // A 16KB + B 16KB per stage
#define G_SMEM (3 * GS_STAGE)             // 98304 (epilogue reuses 67584 B)
#define Y_PITCH 132                       // floats; 528 B rows, 16B aligned

__device__ __forceinline__ void mma_f16(float c[4], uint32_t a0, uint32_t a1,
                                        uint32_t a2, uint32_t a3,
                                        uint32_t b0, uint32_t b1) {
    asm volatile(
        "mma.sync.aligned.m16n8k16.row.col.f32.f16.f16.f32 "
        "{%0,%1,%2,%3},{%4,%5,%6,%7},{%8,%9},{%0,%1,%2,%3};\n"
        : "+f"(c[0]), "+f"(c[1]), "+f"(c[2]), "+f"(c[3])
        : "r"(a0), "r"(a1), "r"(a2), "r"(a3), "r"(b0), "r"(b1));
}

__device__ __forceinline__ void ldsm4(uint32_t& r0, uint32_t& r1, uint32_t& r2,
                                      uint32_t& r3, uint32_t addr) {
    asm volatile("ldmatrix.sync.aligned.m8n8.x4.shared.b16 {%0,%1,%2,%3}, [%4];"
                 : "=r"(r0), "=r"(r1), "=r"(r2), "=r"(r3) : "r"(addr));
}

__device__ __forceinline__ void g_prefetch(uint32_t sbase, int stage, int chunk,
                                           const __half* Ag, const __half* Bg,
                                           int seg, int rr) {
    uint32_t sa = sbase + stage * GS_STAGE, sb = sa + 16384;
    int kof = chunk * 64 + seg * 8;       // half index within row
#pragma unroll
    for (int j = 0; j < 4; j++) {
        int r = rr + j * 32;
        uint32_t so = SMEM_SWZ((uint32_t)(r * 128 + seg * 16));
        cp16(sa + so, Ag + (size_t)r * D_DIM + kof);
        cp16(sb + so, Bg + (size_t)r * D_DIM + kof);
    }
    asm volatile("cp.async.commit_group;" ::: "memory");
}

__global__ void __launch_bounds__(256, 2)
gemm_mma(const float* __restrict__ u, const float* __restrict__ bias,
         float* __restrict__ out) {
    extern __shared__ __align__(1024) char gsm[];
    uint32_t sbase = smem_u32(gsm);
    int tid = threadIdx.x;
    int warp = tid >> 5, lane = tid & 31;
    int g = lane >> 2, t4 = lane & 3;
    int wm = warp & 1, wn = warp >> 1;          // 2x4 warp grid: 64x32 per warp
    int rowBase = blockIdx.y * 128;
    int colBase = blockIdx.x * 128;
    const __half* Ag = g_uh + (size_t)rowBase * D_DIM;
    const __half* Bg = g_wh + (size_t)colBase * D_DIM;
    int seg = tid & 7, rr = tid >> 3;           // 8 x 16B segs per 128B row

    // ldmatrix lane->address offsets (rows 0-15, then +16B column)
    uint32_t lm_off = (uint32_t)((lane & 15) * 128 + (lane >> 4) * 16);

    float acc[4][4][4];
#pragma unroll
    for (int a = 0; a < 4; a++)
#pragma unroll
        for (int b = 0; b < 4; b++)
#pragma unroll
            for (int c = 0; c < 4; c++) acc[a][b][c] = 0.f;

    g_prefetch(sbase, 0, 0, Ag, Bg, seg, rr);
    g_prefetch(sbase, 1, 1, Ag, Bg, seg, rr);

#pragma unroll 1
    for (int i = 0; i < 16; i++) {
        if (i < 15) asm volatile("cp.async.wait_group 1;" ::: "memory");
        else        asm volatile("cp.async.wait_group 0;" ::: "memory");
        __syncthreads();
        if (i < 14) g_prefetch(sbase, (i + 2) % 3, i + 2, Ag, Bg, seg, rr);

        uint32_t sa = sbase + (i % 3) * GS_STAGE, sb = sa + 16384;
#pragma unroll
        for (int ks = 0; ks < 4; ks++) {
            uint32_t afr[4][4], bfr[4][2];
#pragma unroll
            for (int mt = 0; mt < 4; ++mt) {
                uint32_t off = (uint32_t)((wm * 64 + mt * 16) * 128 + ks * 32) + lm_off;
                ldsm4(afr[mt][0], afr[mt][1], afr[mt][2], afr[mt][3],
                      sa + SMEM_SWZ(off));
            }
#pragma unroll
            for (int np = 0; np < 2; ++np) {
                uint32_t off = (uint32_t)((wn * 32 + np * 16) * 128 + ks * 32) + lm_off;
                // r0=b0(n lo8), r1=b0(n hi8), r2=b1(n lo8), r3=b1(n hi8)
                ldsm4(bfr[2 * np][0], bfr[2 * np + 1][0],
                      bfr[2 * np][1], bfr[2 * np + 1][1], sb + SMEM_SWZ(off));
            }
#pragma unroll
            for (int mt = 0; mt < 4; ++mt)
#pragma unroll
                for (int nt = 0; nt < 4; ++nt)
                    mma_f16(acc[mt][nt], afr[mt][0], afr[mt][1], afr[mt][2],
                            afr[mt][3], bfr[nt][0], bfr[nt][1]);
        }
    }

    // ---- stage yconv tile from g_yT (B,D,S): rows=d (512B contiguous in s) ----
    __syncthreads();                       // all warps done reading mainloop smem
    {
        int bIdx = rowBase >> 12;          // 4096 rows per batch
        int s0 = rowBase & (S_LEN - 1);
        const float* Yg = g_yT + ((size_t)(bIdx * D_DIM + colBase)) * S_LEN + s0;
#pragma unroll
        for (int j = 0; j < 16; j++) {
            int t = tid + j * 256;
            int c = t >> 5, k = t & 31;    // c: 0..127 rows(d), k: 16B seg
            cp16(sbase + (uint32_t)(c * (Y_PITCH * 4) + k * 16),
                 Yg + (size_t)c * S_LEN + k * 4);
        }
        asm volatile("cp.async.commit_group;" ::: "memory");
        asm volatile("cp.async.wait_group 0;" ::: "memory");
        __syncthreads();
    }
    const float* ys = (const float*)gsm;   // [128][Y_PITCH], ys[c][sr]

    // epilogue: out = yconv * (acc + bias) + u
#pragma unroll
    for (int mt = 0; mt < 4; ++mt) {
        int sr0 = wm * 64 + mt * 16 + g;   // row offset within tile
        int sr1 = sr0 + 8;
        int r0 = rowBase + sr0, r1 = rowBase + sr1;
#pragma unroll
        for (int nt = 0; nt < 4; ++nt) {
            int cl = wn * 32 + nt * 8 + 2 * t4;   // col offset within tile
            int c0 = colBase + cl;
            float bb0 = bias[c0], bb1 = bias[c0 + 1];

            float y00 = ys[cl * Y_PITCH + sr0],       y01 = ys[(cl + 1) * Y_PITCH + sr0];
            float y10 = ys[cl * Y_PITCH + sr1],       y11 = ys[(cl + 1) * Y_PITCH + sr1];

            float2 uv0 = *(const float2*)(u + (size_t)r0 * D_DIM + c0);
            float2 o0;
            o0.x = y00 * (acc[mt][nt][0] + bb0) + uv0.x;
            o0.y = y01 * (acc[mt][nt][1] + bb1) + uv0.y;
            *(float2*)(out + (size_t)r0 * D_DIM + c0) = o0;

            float2 uv1 = *(const float2*)(u + (size_t)r1 * D_DIM + c0);
            float2 o1;
            o1.x = y10 * (acc[mt][nt][2] + bb0) + uv1.x;
            o1.y = y11 * (acc[mt][nt][3] + bb1) + uv1.y;
            *(float2*)(out + (size_t)r1 * D_DIM + c0) = o1;
        }
    }
}

// ---------------- launcher ----------------------------------------------------
extern "C" void kernel_launch(void* const* d_in, const int* in_sizes, int n_in,
                              void* d_out, int out_size) {
    const float* u    = (const float*)d_in[0];
    const float* W    = (const float*)d_in[1];
    const float* bia  = (const float*)d_in[2];
    const float* filt = (const float*)d_in[3];
    float* out = (float*)d_out;

    cudaFuncSetAttribute(filt_kernel, cudaFuncAttributeMaxDynamicSharedMemorySize, FFT_SMEM);
    cudaFuncSetAttribute(conv_kernel, cudaFuncAttributeMaxDynamicSharedMemorySize, FFT_SMEM);
    cudaFuncSetAttribute(gemm_mma,    cudaFuncAttributeMaxDynamicSharedMemorySize, G_SMEM);

    // order keeps conv_kernel in the ncu-captured slot (#4)
    prep_kernel<<<(D_DIM * D_DIM) / 256, 256>>>(W);
    transpose_u<<<dim3(D_DIM / 32, S_LEN / 32, B_DIM), dim3(32, 8)>>>(u);
    filt_kernel<<<D_DIM, FNT, FFT_SMEM>>>(filt);
    conv_kernel<<<B_DIM * D_DIM, FNT, FFT_SMEM>>>();
    gemm_mma<<<dim3(D_DIM / 128, (B_DIM * S_LEN) / 128), 256, G_SMEM>>>(u, bia, out);
}